// round 15
// baseline (speedup 1.0000x reference)
#include <cuda_runtime.h>
#include <cuda_bf16.h>
#include <stdint.h>
#include <math.h>

// Problem dims (fixed by the reference)
constexpr int Bb = 4;
constexpr int Ss = 2048;
constexpr int Dd = 1024;
constexpr int Hh = 16;
constexpr int Hd = 64;
constexpr int MM = Bb * Ss;  // 8192 rows

// Scratch (allocation-free rule: __device__ globals), 256B-aligned.
__device__ __align__(256) __nv_bfloat16 g_xh[MM * Dd];
__device__ __align__(256) __nv_bfloat16 g_xl[MM * Dd];
__device__ __align__(256) __nv_bfloat16 g_qh[MM * Dd];
__device__ __align__(256) __nv_bfloat16 g_ql[MM * Dd];
__device__ __align__(256) __nv_bfloat16 g_kh[MM * Dd];
__device__ __align__(256) __nv_bfloat16 g_kl[MM * Dd];
__device__ __align__(256) __nv_bfloat16 g_vh[MM * Dd];
__device__ __align__(256) __nv_bfloat16 g_vl[MM * Dd];
__device__ __align__(256) __nv_bfloat16 g_ch[MM * Dd];
__device__ __align__(256) __nv_bfloat16 g_cl[MM * Dd];
__device__ __align__(256) __nv_bfloat16 g_wth[4 * Dd * Dd];
__device__ __align__(256) __nv_bfloat16 g_wtl[4 * Dd * Dd];

// ---------------------------------------------------------------------------
// PTX helpers. No cudaFuncSetAttribute anywhere; smem <= 48KB default.
// ---------------------------------------------------------------------------
#define CP16(smem, gptr) \
    asm volatile("cp.async.cg.shared.global [%0], [%1], 16;" :: "r"(smem), "l"(gptr))
#define CP_COMMIT() asm volatile("cp.async.commit_group;" ::: "memory")
#define CP_WAIT(n)  asm volatile("cp.async.wait_group %0;" :: "n"(n) : "memory")

#define LDSM4(r, addr) \
    asm volatile("ldmatrix.sync.aligned.m8n8.x4.shared.b16 {%0,%1,%2,%3}, [%4];" \
        : "=r"((r)[0]), "=r"((r)[1]), "=r"((r)[2]), "=r"((r)[3]) : "r"(addr))

#define LDSMT4(r, addr) \
    asm volatile("ldmatrix.sync.aligned.m8n8.x4.trans.shared.b16 {%0,%1,%2,%3}, [%4];" \
        : "=r"((r)[0]), "=r"((r)[1]), "=r"((r)[2]), "=r"((r)[3]) : "r"(addr))

#define MMA_BF16(d, a, b) \
    asm volatile("mma.sync.aligned.m16n8k16.row.col.f32.bf16.bf16.f32 " \
        "{%0,%1,%2,%3}, {%4,%5,%6,%7}, {%8,%9}, {%0,%1,%2,%3};" \
        : "+f"((d)[0]), "+f"((d)[1]), "+f"((d)[2]), "+f"((d)[3]) \
        : "r"((a)[0]), "r"((a)[1]), "r"((a)[2]), "r"((a)[3]), \
          "r"((b)[0]), "r"((b)[1]))

// exp2 via the raw MUFU op (no __exp2f device intrinsic exists).
#define EX2(x) asm("ex2.approx.f32 %0, %0;" : "+f"(x))

// Fast hi/lo split of a float pair into two packed bf16x2 — intrinsics only.
__device__ __forceinline__ void split2(float a, float b, uint32_t& h, uint32_t& l) {
    __nv_bfloat162 h2 = __floats2bfloat162_rn(a, b);  // one packed cvt
    h = *(uint32_t*)&h2;
    float ha = __uint_as_float(h << 16);              // low half -> fp32 hi(a)
    float hb = __uint_as_float(h & 0xFFFF0000u);      // high half -> fp32 hi(b)
    __nv_bfloat162 l2 = __floats2bfloat162_rn(a - ha, b - hb);
    l = *(uint32_t*)&l2;
}

// ---------------------------------------------------------------------------
// Split fp32 -> (bf16 hi, bf16 lo residual), elementwise
// ---------------------------------------------------------------------------
__global__ __launch_bounds__(256) void split_hilo_bf16(
    const float* __restrict__ A, __nv_bfloat16* __restrict__ Hi,
    __nv_bfloat16* __restrict__ Lo)
{
    int i = (blockIdx.x * 256 + threadIdx.x) * 4;
    float4 a = *(const float4*)(A + i);
    uint32_t h0, l0, h1, l1;
    split2(a.x, a.y, h0, l0);
    split2(a.z, a.w, h1, l1);
    *(uint32_t*)(Hi + i)     = h0;
    *(uint32_t*)(Hi + i + 2) = h1;
    *(uint32_t*)(Lo + i)     = l0;
    *(uint32_t*)(Lo + i + 2) = l1;
}

// ---------------------------------------------------------------------------
// Transpose + split all 4 weights in ONE launch (blockIdx.z selects W)
// ---------------------------------------------------------------------------
__global__ __launch_bounds__(256) void transpose_split4_bf16(
    const float* __restrict__ W0, const float* __restrict__ W1,
    const float* __restrict__ W2, const float* __restrict__ W3,
    __nv_bfloat16* __restrict__ Th, __nv_bfloat16* __restrict__ Tl)
{
    __shared__ float t[32][33];
    const int z = blockIdx.z;
    const float* W = z == 0 ? W0 : (z == 1 ? W1 : (z == 2 ? W2 : W3));
    const size_t zo = (size_t)z * Dd * Dd;
    const int tx = threadIdx.x, ty = threadIdx.y;
    const int n0 = blockIdx.x * 32, k0 = blockIdx.y * 32;
#pragma unroll
    for (int i = 0; i < 32; i += 8)
        t[ty + i][tx] = W[(size_t)(k0 + ty + i) * Dd + n0 + tx];
    __syncthreads();
#pragma unroll
    for (int i = 0; i < 32; i += 8) {
        float a = t[tx][ty + i];
        __nv_bfloat16 h = __float2bfloat16(a);
        size_t o = zo + (size_t)(n0 + ty + i) * Dd + k0 + tx;
        Th[o] = h;
        Tl[o] = __float2bfloat16(a - __bfloat162float(h));
    }
}

// ---------------------------------------------------------------------------
// bf16x3 mma.sync GEMM, 3-stage single-sync pipeline. Q output is
// pre-scaled by 0.125*log2(e) so attention can use ex2 directly.
// (unchanged from R14, passing)
// ---------------------------------------------------------------------------
constexpr int NKC = Dd / 16;         // 64 K-chunks
constexpr int ARR3 = 128 * 32;       // 4096 B per sub-array
constexpr int STG3 = 4 * ARR3;       // 16384 B per stage
constexpr int GSMEM = 3 * STG3;      // 49152 B

extern __shared__ char dynsmem[];

__global__ __launch_bounds__(256, 2) void gemm_bf16x3(
    const __nv_bfloat16* __restrict__ Ah, const __nv_bfloat16* __restrict__ Al,
    const __nv_bfloat16* __restrict__ Bt_h, const __nv_bfloat16* __restrict__ Bt_l,
    const float* __restrict__ b0, const float* __restrict__ b1,
    const float* __restrict__ b2,
    __nv_bfloat16* __restrict__ o0h, __nv_bfloat16* __restrict__ o0l,
    __nv_bfloat16* __restrict__ o1h, __nv_bfloat16* __restrict__ o1l,
    __nv_bfloat16* __restrict__ o2h, __nv_bfloat16* __restrict__ o2l,
    float* __restrict__ C)
{
    const int K = Dd, N = Dd;
    const uint32_t sb = (uint32_t)__cvta_generic_to_shared(dynsmem);
    const int tid = threadIdx.x;
    const int wid = tid >> 5, lane = tid & 31;
    const int bm = blockIdx.y, bn = blockIdx.x;
    const int sel = bn >> 3, bnl = bn & 7;
    const int wm = wid >> 2, wn = wid & 3;

    const float* bias = sel == 0 ? b0 : (sel == 1 ? b1 : b2);
    __nv_bfloat16* Ch = sel == 0 ? o0h : (sel == 1 ? o1h : o2h);
    __nv_bfloat16* Cl = sel == 0 ? o0l : (sel == 1 ? o1l : o2l);
    const float osc = (C == nullptr && sel == 0) ? 0.18033688011112042f : 1.0f;

    const int lrow = tid >> 1;
    const int lhb = tid & 1;
    const uint32_t woff =
        (uint32_t)(lrow * 32 + ((lhb ^ ((lrow >> 2) & 1)) << 4));
    const __nv_bfloat16* gAh = Ah + (size_t)(bm * 128 + lrow) * K + lhb * 8;
    const __nv_bfloat16* gAl = Al + (size_t)(bm * 128 + lrow) * K + lhb * 8;
    const __nv_bfloat16* gBh = Bt_h + (size_t)(bn * 128 + lrow) * K + lhb * 8;
    const __nv_bfloat16* gBl = Bt_l + (size_t)(bn * 128 + lrow) * K + lhb * 8;

    auto load_stage = [&](int s, int c) {
        const uint32_t st = sb + s * STG3 + woff;
        const size_t go = (size_t)c * 16;
        CP16(st + 0 * ARR3, gAh + go);
        CP16(st + 1 * ARR3, gAl + go);
        CP16(st + 2 * ARR3, gBh + go);
        CP16(st + 3 * ARR3, gBl + go);
        CP_COMMIT();
    };

    const int lt = lane >> 3, ltr = lane & 7;
    const uint32_t aoff =
        (uint32_t)((wm * 64 + ltr + ((lt & 1) << 3)) * 32) +
        ((((lt >> 1) ^ ((ltr >> 2) & 1))) << 4);
    const uint32_t boff =
        (uint32_t)((wn * 32 + ltr + ((lt >> 1) << 3)) * 32) +
        ((((lt & 1) ^ ((ltr >> 2) & 1))) << 4);

    float acc[4][4][4];
#pragma unroll
    for (int mi = 0; mi < 4; mi++)
#pragma unroll
        for (int ni = 0; ni < 4; ni++)
#pragma unroll
            for (int r = 0; r < 4; r++) acc[mi][ni][r] = 0.0f;

    load_stage(0, 0);
    load_stage(1, 1);

    int s = 0;
    for (int c = 0; c < NKC; c++) {
        if (c == NKC - 1) { CP_WAIT(0); } else { CP_WAIT(1); }
        __syncthreads();
        if (c + 2 < NKC) {
            int sn = s + 2; if (sn >= 3) sn -= 3;
            load_stage(sn, c + 2);
        }
        const uint32_t st = sb + s * STG3;

        uint32_t bhf[2][4], blf[2][4];
#pragma unroll
        for (int nip = 0; nip < 2; nip++) {
            LDSM4(bhf[nip], st + 2 * ARR3 + boff + nip * 512);
            LDSM4(blf[nip], st + 3 * ARR3 + boff + nip * 512);
        }
#pragma unroll
        for (int mi = 0; mi < 4; mi++) {
            uint32_t ahf[4], alf[4];
            LDSM4(ahf, st + aoff + mi * 512);
            LDSM4(alf, st + ARR3 + aoff + mi * 512);
#pragma unroll
            for (int ni = 0; ni < 4; ni++) {
                uint32_t* ph = &bhf[ni >> 1][(ni & 1) * 2];
                uint32_t* pl = &blf[ni >> 1][(ni & 1) * 2];
                MMA_BF16(acc[mi][ni], ahf, ph);
                MMA_BF16(acc[mi][ni], ahf, pl);
                MMA_BF16(acc[mi][ni], alf, ph);
            }
        }
        if (++s == 3) s = 0;
    }

    const int r0 = bm * 128 + wm * 64 + (lane >> 2);
    const int c0 = bnl * 128 + wn * 32 + (lane & 3) * 2;
#pragma unroll
    for (int mi = 0; mi < 4; mi++) {
#pragma unroll
        for (int ni = 0; ni < 4; ni++) {
            const int col = c0 + ni * 8;
            const float bx = bias[col], by = bias[col + 1];
            const float v0 = (acc[mi][ni][0] + bx) * osc;
            const float v1 = (acc[mi][ni][1] + by) * osc;
            const float v2 = (acc[mi][ni][2] + bx) * osc;
            const float v3 = (acc[mi][ni][3] + by) * osc;
            const size_t o0 = (size_t)(r0 + mi * 16) * N + col;
            const size_t o1 = (size_t)(r0 + mi * 16 + 8) * N + col;
            if (C) {
                float2 a0; a0.x = v0; a0.y = v1;
                float2 a1; a1.x = v2; a1.y = v3;
                *(float2*)(C + o0) = a0;
                *(float2*)(C + o1) = a1;
            } else {
                uint32_t h, l;
                split2(v0, v1, h, l);
                *(uint32_t*)(Ch + o0) = h;
                *(uint32_t*)(Cl + o0) = l;
                split2(v2, v3, h, l);
                *(uint32_t*)(Ch + o1) = h;
                *(uint32_t*)(Cl + o1) = l;
            }
        }
    }
}

// ---------------------------------------------------------------------------
// Flash attention, bf16x3 mma.sync, causal — TWO DE-PHASED HALF-CTAS.
// Warps 0-3 own q rows 0-63, warps 4-7 rows 64-127. Each group has its own
// 3-stage 16-key K/V ring (24KB; 48KB total) and its own named barrier, so
// the groups free-run: one group's softmax overlaps the other's MMAs (one
// warp of each group per SMSP). Static-max softmax (tile-order independent),
// Q pre-scaled by 0.125*log2e -> p = ex2(S). Group A skips its 4 fully-
// masked tail tiles. (R11 structure, now on the proven R14 arithmetic.)
// ---------------------------------------------------------------------------
constexpr int AQT = 128;
constexpr int GKT = 16;               // keys per tile per group
constexpr int GARR = GKT * 128;       // 2048 B per array
constexpr int GSTG = 4 * GARR;        // 8192 B per stage (Kh, Kl, Vh, Vl)
constexpr int GRING = 3 * GSTG;       // 24576 B per group
constexpr int ASMEM = 2 * GRING;      // 49152 = default smem limit

__global__ __launch_bounds__(256, 2) void attn_bf16(
    const __nv_bfloat16* __restrict__ Qh, const __nv_bfloat16* __restrict__ Ql,
    const __nv_bfloat16* __restrict__ Kh, const __nv_bfloat16* __restrict__ Kl,
    const __nv_bfloat16* __restrict__ Vh, const __nv_bfloat16* __restrict__ Vl,
    __nv_bfloat16* __restrict__ Ch, __nv_bfloat16* __restrict__ Cl)
{
    const uint32_t sb = (uint32_t)__cvta_generic_to_shared(dynsmem);
    const int tid = threadIdx.x;
    const int grp = tid >> 7;          // half-CTA id (0 or 1)
    const int gtid = tid & 127;
    const int w = tid >> 5, lane = tid & 31;
    const int qt = (int)gridDim.x - 1 - (int)blockIdx.x;  // longest first
    const int b = blockIdx.y >> 4, h = blockIdx.y & 15;
    const size_t base = ((size_t)b * Ss) * Dd + (size_t)h * Hd;
    const int nkt = 8 * qt + 4 * (grp + 1);   // group A skips masked tail
    const int lt = lane >> 3, ltr = lane & 7;

    // ---- Stage Q hi/lo through smem (all 256 threads), extract frags ----
    {
#pragma unroll
        for (int i = 0; i < 4; i++) {
            const int ch = tid + i * 256;
            const int row = ch >> 3, cc = ch & 7;
            const uint32_t so =
                (uint32_t)(row * 128 + ((cc ^ (row & 7)) << 4));
            const size_t go = base + (size_t)(qt * AQT + row) * Dd + cc * 8;
            CP16(sb + so,         Qh + go);
            CP16(sb + 16384 + so, Ql + go);
        }
        CP_COMMIT();
        CP_WAIT(0);
        __syncthreads();
    }
    uint32_t qhf[4][4], qlf[4][4];
    {
        const int qr = w * 16 + ltr + ((lt & 1) << 3);
        const uint32_t qrow = (uint32_t)(qr * 128);
#pragma unroll
        for (int ks = 0; ks < 4; ks++) {
            const uint32_t off =
                qrow + (((uint32_t)((2 * ks + (lt >> 1)) ^ ltr)) << 4);
            LDSM4(qhf[ks], sb + off);
            LDSM4(qlf[ks], sb + 16384 + off);
        }
    }
    __syncthreads();   // both groups done reading Q before rings overwrite

    // ---- per-group K/V tile loader (128 threads, 1 chunk/array each) ----
    const uint32_t rb = sb + grp * GRING;
    const int lrow = gtid >> 3, lcc = gtid & 7;   // 16 rows x 8 chunks
    const uint32_t lso = (uint32_t)(lrow * 128 + ((lcc ^ (lrow & 7)) << 4));
    auto load_kv = [&](int c, int s) {
        const uint32_t st = rb + s * GSTG;
        const size_t go = base + (size_t)(c * GKT + lrow) * Dd + lcc * 8;
        CP16(st + 0 * GARR + lso, Kh + go);
        CP16(st + 1 * GARR + lso, Kl + go);
        CP16(st + 2 * GARR + lso, Vh + go);
        CP16(st + 3 * GARR + lso, Vl + go);
        CP_COMMIT();
    };

    const uint32_t kb_row = (uint32_t)((ltr + ((lt >> 1) << 3)) * 128);
    const uint32_t vb_row = (uint32_t)((ltr + ((lt & 1) << 3)) * 128);
    const int kc0 = lt & 1;
    const int vc0 = lt >> 1;

    float oacc[8][4];
#pragma unroll
    for (int nb = 0; nb < 8; nb++)
#pragma unroll
        for (int r = 0; r < 4; r++) oacc[nb][r] = 0.0f;
    float ls0 = 0.0f, ls1 = 0.0f;

    load_kv(0, 0);
    load_kv(1, 1);

    const int barid = 1 + grp;
    int s = 0;
    for (int c = 0; c < nkt; c++) {
        if (c == nkt - 1) { CP_WAIT(0); } else { CP_WAIT(1); }
        asm volatile("bar.sync %0, 128;" :: "r"(barid) : "memory");
        if (c + 2 < nkt) {
            int sn = s + 2; if (sn >= 3) sn -= 3;
            load_kv(c + 2, sn);
        }
        const uint32_t st = rb + s * GSTG;

        // ---- S = Q K^T (3-term bf16): 16 q-rows x 16 keys per warp ----
        float sacc[2][4];
#pragma unroll
        for (int nb = 0; nb < 2; nb++)
#pragma unroll
            for (int r = 0; r < 4; r++) sacc[nb][r] = 0.0f;

#pragma unroll
        for (int ks = 0; ks < 4; ks++) {
            uint32_t kh4[4], kl4[4];
            const uint32_t a = st + kb_row +
                (((uint32_t)((2 * ks + kc0) ^ ltr)) << 4);
            LDSM4(kh4, a);
            LDSM4(kl4, a + GARR);
            MMA_BF16(sacc[0], qhf[ks], kh4);
            MMA_BF16(sacc[0], qhf[ks], kl4);
            MMA_BF16(sacc[0], qlf[ks], kh4);
            MMA_BF16(sacc[1], qhf[ks], kh4 + 2);
            MMA_BF16(sacc[1], qhf[ks], kl4 + 2);
            MMA_BF16(sacc[1], qlf[ks], kh4 + 2);
        }

        // ---- static-max softmax via ex2 (Q pre-scaled by log2e/8) ----
        const bool diag = (c >= 8 * qt + 4 * grp);
        const int row0 = qt * AQT + w * 16 + (lane >> 2);
        float lo0 = 0.0f, lo1 = 0.0f;
#pragma unroll
        for (int nb = 0; nb < 2; nb++) {
            float s0 = sacc[nb][0], s1 = sacc[nb][1];
            float s2 = sacc[nb][2], s3 = sacc[nb][3];
            if (diag) {
                const int col = c * GKT + nb * 8 + (lane & 3) * 2;
                if (col     > row0)     s0 = -1e30f;
                if (col + 1 > row0)     s1 = -1e30f;
                if (col     > row0 + 8) s2 = -1e30f;
                if (col + 1 > row0 + 8) s3 = -1e30f;
            }
            EX2(s0); EX2(s1); EX2(s2); EX2(s3);
            sacc[nb][0] = s0; sacc[nb][1] = s1;
            sacc[nb][2] = s2; sacc[nb][3] = s3;
            lo0 += s0 + s1;
            lo1 += s2 + s3;
        }
        ls0 += lo0;
        ls1 += lo1;

        // ---- O += P V (3-term bf16; V^T frags via ldmatrix.trans) ----
        uint32_t phf4[4], plf4[4];
        split2(sacc[0][0], sacc[0][1], phf4[0], plf4[0]);
        split2(sacc[0][2], sacc[0][3], phf4[1], plf4[1]);
        split2(sacc[1][0], sacc[1][1], phf4[2], plf4[2]);
        split2(sacc[1][2], sacc[1][3], phf4[3], plf4[3]);
#pragma unroll
        for (int dg = 0; dg < 4; dg++) {
            uint32_t vh4[4], vl4[4];
            const uint32_t a = st + 2 * GARR + vb_row +
                (((uint32_t)((2 * dg + vc0) ^ ltr)) << 4);
            LDSMT4(vh4, a);
            LDSMT4(vl4, a + GARR);
            MMA_BF16(oacc[2 * dg],     phf4, vh4);
            MMA_BF16(oacc[2 * dg],     phf4, vl4);
            MMA_BF16(oacc[2 * dg],     plf4, vh4);
            MMA_BF16(oacc[2 * dg + 1], phf4, vh4 + 2);
            MMA_BF16(oacc[2 * dg + 1], phf4, vl4 + 2);
            MMA_BF16(oacc[2 * dg + 1], plf4, vh4 + 2);
        }
        if (++s == 3) s = 0;
    }

    // ---- final row-sum reduce + normalize + write ctx as bf16 hi/lo ----
    ls0 += __shfl_xor_sync(0xffffffffu, ls0, 1);
    ls0 += __shfl_xor_sync(0xffffffffu, ls0, 2);
    ls1 += __shfl_xor_sync(0xffffffffu, ls1, 1);
    ls1 += __shfl_xor_sync(0xffffffffu, ls1, 2);
    const float inv0 = 1.0f / ls0, inv1 = 1.0f / ls1;
    const size_t tr0 = (size_t)(b * Ss + qt * AQT + w * 16 + (lane >> 2));
    const int dcol = h * Hd + (lane & 3) * 2;
#pragma unroll
    for (int nb = 0; nb < 8; nb++) {
        const float o0 = oacc[nb][0] * inv0, o1 = oacc[nb][1] * inv0;
        const float o2 = oacc[nb][2] * inv1, o3 = oacc[nb][3] * inv1;
        const size_t g0 = tr0 * Dd + dcol + nb * 8;
        const size_t g1 = (tr0 + 8) * Dd + dcol + nb * 8;
        uint32_t hh, ll;
        split2(o0, o1, hh, ll);
        *(uint32_t*)(Ch + g0) = hh;
        *(uint32_t*)(Cl + g0) = ll;
        split2(o2, o3, hh, ll);
        *(uint32_t*)(Ch + g1) = hh;
        *(uint32_t*)(Cl + g1) = ll;
    }
}

// ---------------------------------------------------------------------------
extern "C" void kernel_launch(void* const* d_in, const int* in_sizes, int n_in,
                              void* d_out, int out_size)
{
    const float* x  = (const float*)d_in[0];
    const float* Wq = (const float*)d_in[1];
    const float* bq = (const float*)d_in[2];
    const float* Wk = (const float*)d_in[3];
    const float* bk = (const float*)d_in[4];
    const float* Wv = (const float*)d_in[5];
    const float* bv = (const float*)d_in[6];
    const float* Wo = (const float*)d_in[7];
    const float* bo = (const float*)d_in[8];
    float* out = (float*)d_out;

    __nv_bfloat16 *xh, *xl, *qh, *ql, *kh, *kl, *vh, *vl, *ch, *cl, *wth, *wtl;
    cudaGetSymbolAddress((void**)&xh, g_xh);
    cudaGetSymbolAddress((void**)&xl, g_xl);
    cudaGetSymbolAddress((void**)&qh, g_qh);
    cudaGetSymbolAddress((void**)&ql, g_ql);
    cudaGetSymbolAddress((void**)&kh, g_kh);
    cudaGetSymbolAddress((void**)&kl, g_kl);
    cudaGetSymbolAddress((void**)&vh, g_vh);
    cudaGetSymbolAddress((void**)&vl, g_vl);
    cudaGetSymbolAddress((void**)&ch, g_ch);
    cudaGetSymbolAddress((void**)&cl, g_cl);
    cudaGetSymbolAddress((void**)&wth, g_wth);
    cudaGetSymbolAddress((void**)&wtl, g_wtl);

    const int WSZ = Dd * Dd;

    transpose_split4_bf16<<<dim3(32, 32, 4), dim3(32, 8)>>>(Wq, Wk, Wv, Wo, wth, wtl);

    split_hilo_bf16<<<(MM * Dd) / 1024, 256>>>(x, xh, xl);

    gemm_bf16x3<<<dim3(24, MM / 128), 256, GSMEM>>>(
        xh, xl, wth, wtl, bq, bk, bv,
        qh, ql, kh, kl, vh, vl, nullptr);

    attn_bf16<<<dim3(Ss / AQT, Bb * Hh), 256, ASMEM>>>(qh, ql, kh, kl, vh, vl, ch, cl);

    gemm_bf16x3<<<dim3(8, MM / 128), 256, GSMEM>>>(
        ch, cl, wth + 3 * (size_t)WSZ, wtl + 3 * (size_t)WSZ, bo, bo, bo,
        nullptr, nullptr, nullptr, nullptr, nullptr, nullptr, out);
}

// round 17
// speedup vs baseline: 1.1272x; 1.1272x over previous
#include <cuda_runtime.h>
#include <cuda_bf16.h>
#include <cuda_fp16.h>
#include <stdint.h>
#include <math.h>

// Problem dims (fixed by the reference)
constexpr int Bb = 4;
constexpr int Ss = 2048;
constexpr int Dd = 1024;
constexpr int Hh = 16;
constexpr int Hd = 64;
constexpr int MM = Bb * Ss;  // 8192 rows

// Scratch (allocation-free rule: __device__ globals), 256B-aligned.
// qh/ql/kh/vh hold fp16 bits; ch/cl hold bf16 bits (16-bit raw storage).
__device__ __align__(256) __nv_bfloat16 g_xh[MM * Dd];
__device__ __align__(256) __nv_bfloat16 g_xl[MM * Dd];
__device__ __align__(256) __nv_bfloat16 g_qh[MM * Dd];
__device__ __align__(256) __nv_bfloat16 g_ql[MM * Dd];
__device__ __align__(256) __nv_bfloat16 g_kh[MM * Dd];
__device__ __align__(256) __nv_bfloat16 g_vh[MM * Dd];
__device__ __align__(256) __nv_bfloat16 g_ch[MM * Dd];
__device__ __align__(256) __nv_bfloat16 g_cl[MM * Dd];
__device__ __align__(256) __nv_bfloat16 g_wth[4 * Dd * Dd];
__device__ __align__(256) __nv_bfloat16 g_wtl[4 * Dd * Dd];

// ---------------------------------------------------------------------------
// PTX helpers. No cudaFuncSetAttribute anywhere; smem <= 48KB default.
// ---------------------------------------------------------------------------
#define CP16(smem, gptr) \
    asm volatile("cp.async.cg.shared.global [%0], [%1], 16;" :: "r"(smem), "l"(gptr))
#define CP_COMMIT() asm volatile("cp.async.commit_group;" ::: "memory")
#define CP_WAIT(n)  asm volatile("cp.async.wait_group %0;" :: "n"(n) : "memory")

#define LDSM4(r, addr) \
    asm volatile("ldmatrix.sync.aligned.m8n8.x4.shared.b16 {%0,%1,%2,%3}, [%4];" \
        : "=r"((r)[0]), "=r"((r)[1]), "=r"((r)[2]), "=r"((r)[3]) : "r"(addr))

#define LDSMT4(r, addr) \
    asm volatile("ldmatrix.sync.aligned.m8n8.x4.trans.shared.b16 {%0,%1,%2,%3}, [%4];" \
        : "=r"((r)[0]), "=r"((r)[1]), "=r"((r)[2]), "=r"((r)[3]) : "r"(addr))

#define MMA_BF16(d, a, b) \
    asm volatile("mma.sync.aligned.m16n8k16.row.col.f32.bf16.bf16.f32 " \
        "{%0,%1,%2,%3}, {%4,%5,%6,%7}, {%8,%9}, {%0,%1,%2,%3};" \
        : "+f"((d)[0]), "+f"((d)[1]), "+f"((d)[2]), "+f"((d)[3]) \
        : "r"((a)[0]), "r"((a)[1]), "r"((a)[2]), "r"((a)[3]), \
          "r"((b)[0]), "r"((b)[1]))

#define MMA_F16(d, a, b) \
    asm volatile("mma.sync.aligned.m16n8k16.row.col.f32.f16.f16.f32 " \
        "{%0,%1,%2,%3}, {%4,%5,%6,%7}, {%8,%9}, {%0,%1,%2,%3};" \
        : "+f"((d)[0]), "+f"((d)[1]), "+f"((d)[2]), "+f"((d)[3]) \
        : "r"((a)[0]), "r"((a)[1]), "r"((a)[2]), "r"((a)[3]), \
          "r"((b)[0]), "r"((b)[1]))

// exp2 via the raw MUFU op (no __exp2f device intrinsic exists).
#define EX2(x) asm("ex2.approx.f32 %0, %0;" : "+f"(x))

// Fast hi/lo split of a float pair into two packed bf16x2 — intrinsics only.
__device__ __forceinline__ void split2(float a, float b, uint32_t& h, uint32_t& l) {
    __nv_bfloat162 h2 = __floats2bfloat162_rn(a, b);
    h = *(uint32_t*)&h2;
    float ha = __uint_as_float(h << 16);
    float hb = __uint_as_float(h & 0xFFFF0000u);
    __nv_bfloat162 l2 = __floats2bfloat162_rn(a - ha, b - hb);
    l = *(uint32_t*)&l2;
}

// fp16 hi/lo split of a float pair into two packed half2.
__device__ __forceinline__ void split2h(float a, float b, uint32_t& h, uint32_t& l) {
    __half2 h2 = __floats2half2_rn(a, b);
    h = *(uint32_t*)&h2;
    float ha = __half2float(__low2half(h2));
    float hb = __half2float(__high2half(h2));
    __half2 l2 = __floats2half2_rn(a - ha, b - hb);
    l = *(uint32_t*)&l2;
}

__device__ __forceinline__ uint32_t pack2h(float a, float b) {
    __half2 t = __floats2half2_rn(a, b);
    return *(uint32_t*)&t;
}

// ---------------------------------------------------------------------------
// Split fp32 -> (bf16 hi, bf16 lo residual), elementwise
// ---------------------------------------------------------------------------
__global__ __launch_bounds__(256) void split_hilo_bf16(
    const float* __restrict__ A, __nv_bfloat16* __restrict__ Hi,
    __nv_bfloat16* __restrict__ Lo)
{
    int i = (blockIdx.x * 256 + threadIdx.x) * 4;
    float4 a = *(const float4*)(A + i);
    uint32_t h0, l0, h1, l1;
    split2(a.x, a.y, h0, l0);
    split2(a.z, a.w, h1, l1);
    *(uint32_t*)(Hi + i)     = h0;
    *(uint32_t*)(Hi + i + 2) = h1;
    *(uint32_t*)(Lo + i)     = l0;
    *(uint32_t*)(Lo + i + 2) = l1;
}

// ---------------------------------------------------------------------------
// Transpose + split all 4 weights in ONE launch (blockIdx.z selects W)
// ---------------------------------------------------------------------------
__global__ __launch_bounds__(256) void transpose_split4_bf16(
    const float* __restrict__ W0, const float* __restrict__ W1,
    const float* __restrict__ W2, const float* __restrict__ W3,
    __nv_bfloat16* __restrict__ Th, __nv_bfloat16* __restrict__ Tl)
{
    __shared__ float t[32][33];
    const int z = blockIdx.z;
    const float* W = z == 0 ? W0 : (z == 1 ? W1 : (z == 2 ? W2 : W3));
    const size_t zo = (size_t)z * Dd * Dd;
    const int tx = threadIdx.x, ty = threadIdx.y;
    const int n0 = blockIdx.x * 32, k0 = blockIdx.y * 32;
#pragma unroll
    for (int i = 0; i < 32; i += 8)
        t[ty + i][tx] = W[(size_t)(k0 + ty + i) * Dd + n0 + tx];
    __syncthreads();
#pragma unroll
    for (int i = 0; i < 32; i += 8) {
        float a = t[tx][ty + i];
        __nv_bfloat16 h = __float2bfloat16(a);
        size_t o = zo + (size_t)(n0 + ty + i) * Dd + k0 + tx;
        Th[o] = h;
        Tl[o] = __float2bfloat16(a - __bfloat162float(h));
    }
}

// ---------------------------------------------------------------------------
// bf16x3 mma.sync GEMM, 3-stage single-sync pipeline.
// bf16-out modes: Cl!=null -> fp16 hi/lo split (Q, pre-scaled by log2e/8);
//                 Cl==null -> single fp16 (K, V).
// fp32 mode (C != null) for the output projection.
// ---------------------------------------------------------------------------
constexpr int NKC = Dd / 16;         // 64 K-chunks
constexpr int ARR3 = 128 * 32;       // 4096 B per sub-array
constexpr int STG3 = 4 * ARR3;       // 16384 B per stage
constexpr int GSMEM = 3 * STG3;      // 49152 B

extern __shared__ char dynsmem[];

__global__ __launch_bounds__(256, 2) void gemm_bf16x3(
    const __nv_bfloat16* __restrict__ Ah, const __nv_bfloat16* __restrict__ Al,
    const __nv_bfloat16* __restrict__ Bt_h, const __nv_bfloat16* __restrict__ Bt_l,
    const float* __restrict__ b0, const float* __restrict__ b1,
    const float* __restrict__ b2,
    __nv_bfloat16* __restrict__ o0h, __nv_bfloat16* __restrict__ o0l,
    __nv_bfloat16* __restrict__ o1h, __nv_bfloat16* __restrict__ o1l,
    __nv_bfloat16* __restrict__ o2h, __nv_bfloat16* __restrict__ o2l,
    float* __restrict__ C)
{
    const int K = Dd, N = Dd;
    const uint32_t sb = (uint32_t)__cvta_generic_to_shared(dynsmem);
    const int tid = threadIdx.x;
    const int wid = tid >> 5, lane = tid & 31;
    const int bm = blockIdx.y, bn = blockIdx.x;
    const int sel = bn >> 3, bnl = bn & 7;
    const int wm = wid >> 2, wn = wid & 3;

    const float* bias = sel == 0 ? b0 : (sel == 1 ? b1 : b2);
    __nv_bfloat16* Ch = sel == 0 ? o0h : (sel == 1 ? o1h : o2h);
    __nv_bfloat16* Cl = sel == 0 ? o0l : (sel == 1 ? o1l : o2l);
    // Q (sel 0): fold 1/sqrt(64) * log2(e) so attn uses ex2.
    const float osc = (C == nullptr && sel == 0) ? 0.18033688011112042f : 1.0f;

    const int lrow = tid >> 1;
    const int lhb = tid & 1;
    const uint32_t woff =
        (uint32_t)(lrow * 32 + ((lhb ^ ((lrow >> 2) & 1)) << 4));
    const __nv_bfloat16* gAh = Ah + (size_t)(bm * 128 + lrow) * K + lhb * 8;
    const __nv_bfloat16* gAl = Al + (size_t)(bm * 128 + lrow) * K + lhb * 8;
    const __nv_bfloat16* gBh = Bt_h + (size_t)(bn * 128 + lrow) * K + lhb * 8;
    const __nv_bfloat16* gBl = Bt_l + (size_t)(bn * 128 + lrow) * K + lhb * 8;

    auto load_stage = [&](int s, int c) {
        const uint32_t st = sb + s * STG3 + woff;
        const size_t go = (size_t)c * 16;
        CP16(st + 0 * ARR3, gAh + go);
        CP16(st + 1 * ARR3, gAl + go);
        CP16(st + 2 * ARR3, gBh + go);
        CP16(st + 3 * ARR3, gBl + go);
        CP_COMMIT();
    };

    const int lt = lane >> 3, ltr = lane & 7;
    const uint32_t aoff =
        (uint32_t)((wm * 64 + ltr + ((lt & 1) << 3)) * 32) +
        ((((lt >> 1) ^ ((ltr >> 2) & 1))) << 4);
    const uint32_t boff =
        (uint32_t)((wn * 32 + ltr + ((lt >> 1) << 3)) * 32) +
        ((((lt & 1) ^ ((ltr >> 2) & 1))) << 4);

    float acc[4][4][4];
#pragma unroll
    for (int mi = 0; mi < 4; mi++)
#pragma unroll
        for (int ni = 0; ni < 4; ni++)
#pragma unroll
            for (int r = 0; r < 4; r++) acc[mi][ni][r] = 0.0f;

    load_stage(0, 0);
    load_stage(1, 1);

    int s = 0;
    for (int c = 0; c < NKC; c++) {
        if (c == NKC - 1) { CP_WAIT(0); } else { CP_WAIT(1); }
        __syncthreads();
        if (c + 2 < NKC) {
            int sn = s + 2; if (sn >= 3) sn -= 3;
            load_stage(sn, c + 2);
        }
        const uint32_t st = sb + s * STG3;

        uint32_t bhf[2][4], blf[2][4];
#pragma unroll
        for (int nip = 0; nip < 2; nip++) {
            LDSM4(bhf[nip], st + 2 * ARR3 + boff + nip * 512);
            LDSM4(blf[nip], st + 3 * ARR3 + boff + nip * 512);
        }
#pragma unroll
        for (int mi = 0; mi < 4; mi++) {
            uint32_t ahf[4], alf[4];
            LDSM4(ahf, st + aoff + mi * 512);
            LDSM4(alf, st + ARR3 + aoff + mi * 512);
#pragma unroll
            for (int ni = 0; ni < 4; ni++) {
                uint32_t* ph = &bhf[ni >> 1][(ni & 1) * 2];
                uint32_t* pl = &blf[ni >> 1][(ni & 1) * 2];
                MMA_BF16(acc[mi][ni], ahf, ph);
                MMA_BF16(acc[mi][ni], ahf, pl);
                MMA_BF16(acc[mi][ni], alf, ph);
            }
        }
        if (++s == 3) s = 0;
    }

    const int r0 = bm * 128 + wm * 64 + (lane >> 2);
    const int c0 = bnl * 128 + wn * 32 + (lane & 3) * 2;
#pragma unroll
    for (int mi = 0; mi < 4; mi++) {
#pragma unroll
        for (int ni = 0; ni < 4; ni++) {
            const int col = c0 + ni * 8;
            const float bx = bias[col], by = bias[col + 1];
            const float v0 = (acc[mi][ni][0] + bx) * osc;
            const float v1 = (acc[mi][ni][1] + by) * osc;
            const float v2 = (acc[mi][ni][2] + bx) * osc;
            const float v3 = (acc[mi][ni][3] + by) * osc;
            const size_t o0 = (size_t)(r0 + mi * 16) * N + col;
            const size_t o1 = (size_t)(r0 + mi * 16 + 8) * N + col;
            if (C) {
                float2 a0; a0.x = v0; a0.y = v1;
                float2 a1; a1.x = v2; a1.y = v3;
                *(float2*)(C + o0) = a0;
                *(float2*)(C + o1) = a1;
            } else if (Cl) {
                uint32_t h, l;
                split2h(v0, v1, h, l);
                *(uint32_t*)(Ch + o0) = h;
                *(uint32_t*)(Cl + o0) = l;
                split2h(v2, v3, h, l);
                *(uint32_t*)(Ch + o1) = h;
                *(uint32_t*)(Cl + o1) = l;
            } else {
                *(uint32_t*)(Ch + o0) = pack2h(v0, v1);
                *(uint32_t*)(Ch + o1) = pack2h(v2, v3);
            }
        }
    }
}

// ---------------------------------------------------------------------------
// Flash attention, fp16 mma.sync, causal — STATIC-MAX softmax via ex2.
// Precision plan: Q = fp16 hi/lo (exact-ish), K = single fp16 (~2e-4),
// V = single fp16 (~2e-4), P = fp16 hi/lo (exact-ish). S and PV are
// 2-term products -> attention MMA count is 2/3 of the bf16x3 version,
// K/V ldsm and smem traffic halved.
// 64-key stages (K 8KB + V 8KB = 16KB x 3 = 48KB), processed as two
// 32-key sub-tiles to keep register pressure at the proven R14 level.
// ---------------------------------------------------------------------------
constexpr int AQT = 128;
constexpr int AKT = 64;
constexpr int KARR2 = AKT * 128;      // 8192 per array (K or V)
constexpr int ASTG = 2 * KARR2;       // 16384 per stage
constexpr int ASMEM = 3 * ASTG;       // 49152 = default smem limit

__global__ __launch_bounds__(256, 2) void attn_f16(
    const __nv_bfloat16* __restrict__ Qh, const __nv_bfloat16* __restrict__ Ql,
    const __nv_bfloat16* __restrict__ K16, const __nv_bfloat16* __restrict__ V16,
    __nv_bfloat16* __restrict__ Ch, __nv_bfloat16* __restrict__ Cl)
{
    const uint32_t sb = (uint32_t)__cvta_generic_to_shared(dynsmem);
    const int tid = threadIdx.x;
    const int w = tid >> 5, lane = tid & 31;
    const int qt = (int)gridDim.x - 1 - (int)blockIdx.x;  // longest first
    const int b = blockIdx.y >> 4, h = blockIdx.y & 15;
    const size_t base = ((size_t)b * Ss) * Dd + (size_t)h * Hd;
    const int nkt = 2 * (qt + 1);
    const int lt = lane >> 3, ltr = lane & 7;

    // ---- Stage Q hi/lo through smem (first 32KB), extract frags ----
    {
#pragma unroll
        for (int i = 0; i < 4; i++) {
            const int ch = tid + i * 256;
            const int row = ch >> 3, cc = ch & 7;
            const uint32_t so =
                (uint32_t)(row * 128 + ((cc ^ (row & 7)) << 4));
            const size_t go = base + (size_t)(qt * AQT + row) * Dd + cc * 8;
            CP16(sb + so,         Qh + go);
            CP16(sb + 16384 + so, Ql + go);
        }
        CP_COMMIT();
        CP_WAIT(0);
        __syncthreads();
    }
    uint32_t qhf[4][4], qlf[4][4];
    {
        const int qr = w * 16 + ltr + ((lt & 1) << 3);
        const uint32_t qrow = (uint32_t)(qr * 128);
#pragma unroll
        for (int ks = 0; ks < 4; ks++) {
            const uint32_t off =
                qrow + (((uint32_t)((2 * ks + (lt >> 1)) ^ ltr)) << 4);
            LDSM4(qhf[ks], sb + off);
            LDSM4(qlf[ks], sb + 16384 + off);
        }
    }
    __syncthreads();

    // ---- K/V tile loader: 64 rows x 8 chunks, 2 chunks/thread/array ----
    auto load_kv = [&](int c, int s) {
        const uint32_t st = sb + s * ASTG;
#pragma unroll
        for (int i = 0; i < 2; i++) {
            const int ch = tid + i * 256;
            const int row = ch >> 3, cc = ch & 7;
            const uint32_t so = (uint32_t)(row * 128 + ((cc ^ (row & 7)) << 4));
            const size_t go = base + (size_t)(c * AKT + row) * Dd + cc * 8;
            CP16(st + so,          K16 + go);
            CP16(st + KARR2 + so,  V16 + go);
        }
        CP_COMMIT();
    };

    const uint32_t kb_row = (uint32_t)((ltr + ((lt >> 1) << 3)) * 128);
    const uint32_t vb_row = (uint32_t)((ltr + ((lt & 1) << 3)) * 128);
    const int kc0 = lt & 1;
    const int vc0 = lt >> 1;

    float oacc[8][4];
#pragma unroll
    for (int nb = 0; nb < 8; nb++)
#pragma unroll
        for (int r = 0; r < 4; r++) oacc[nb][r] = 0.0f;
    float ls0 = 0.0f, ls1 = 0.0f;   // lane-local exp sums (reduced at end)

    load_kv(0, 0);
    load_kv(1, 1);

    int s = 0;
    for (int c = 0; c < nkt; c++) {
        if (c == nkt - 1) { CP_WAIT(0); } else { CP_WAIT(1); }
        __syncthreads();
        if (c + 2 < nkt) {
            int sn = s + 2; if (sn >= 3) sn -= 3;
            load_kv(c + 2, sn);
        }
        const uint32_t st = sb + s * ASTG;
        const bool diag = (c >= 2 * qt);
        const int row0 = qt * AQT + w * 16 + (lane >> 2);

#pragma unroll
        for (int sub = 0; sub < 2; sub++) {
            const uint32_t stk = st + sub * 4096;          // K rows sub*32..
            const uint32_t stv = st + KARR2 + sub * 4096;  // V rows sub*32..

            // ---- S = Q K^T (2-term fp16): 128 q x 32 keys ----
            float sacc[4][4];
#pragma unroll
            for (int nb = 0; nb < 4; nb++)
#pragma unroll
                for (int r = 0; r < 4; r++) sacc[nb][r] = 0.0f;

#pragma unroll
            for (int ks = 0; ks < 4; ks++) {
#pragma unroll
                for (int ng = 0; ng < 2; ng++) {
                    uint32_t k4[4];
                    const uint32_t a = stk + kb_row + ng * 2048 +
                        (((uint32_t)((2 * ks + kc0) ^ ltr)) << 4);
                    LDSM4(k4, a);
                    MMA_F16(sacc[2 * ng],     qhf[ks], k4);
                    MMA_F16(sacc[2 * ng],     qlf[ks], k4);
                    MMA_F16(sacc[2 * ng + 1], qhf[ks], k4 + 2);
                    MMA_F16(sacc[2 * ng + 1], qlf[ks], k4 + 2);
                }
            }

            // ---- static-max softmax via ex2 (Q pre-scaled by log2e/8) ----
            float lo0 = 0.0f, lo1 = 0.0f;
#pragma unroll
            for (int nb = 0; nb < 4; nb++) {
                float s0 = sacc[nb][0], s1 = sacc[nb][1];
                float s2 = sacc[nb][2], s3 = sacc[nb][3];
                if (diag) {
                    const int col = c * AKT + sub * 32 + nb * 8 + (lane & 3) * 2;
                    if (col     > row0)     s0 = -1e30f;
                    if (col + 1 > row0)     s1 = -1e30f;
                    if (col     > row0 + 8) s2 = -1e30f;
                    if (col + 1 > row0 + 8) s3 = -1e30f;
                }
                EX2(s0); EX2(s1); EX2(s2); EX2(s3);
                sacc[nb][0] = s0; sacc[nb][1] = s1;
                sacc[nb][2] = s2; sacc[nb][3] = s3;
                lo0 += s0 + s1;
                lo1 += s2 + s3;
            }
            ls0 += lo0;
            ls1 += lo1;

            // ---- O += P V (2-term fp16: P hi/lo x V single) ----
#pragma unroll
            for (int ks = 0; ks < 2; ks++) {
                uint32_t phf4[4], plf4[4];
                split2h(sacc[2 * ks][0], sacc[2 * ks][1], phf4[0], plf4[0]);
                split2h(sacc[2 * ks][2], sacc[2 * ks][3], phf4[1], plf4[1]);
                split2h(sacc[2 * ks + 1][0], sacc[2 * ks + 1][1], phf4[2], plf4[2]);
                split2h(sacc[2 * ks + 1][2], sacc[2 * ks + 1][3], phf4[3], plf4[3]);
#pragma unroll
                for (int dg = 0; dg < 4; dg++) {
                    uint32_t v4[4];
                    const uint32_t a = stv + vb_row + ks * 2048 +
                        (((uint32_t)((2 * dg + vc0) ^ ltr)) << 4);
                    LDSMT4(v4, a);
                    MMA_F16(oacc[2 * dg],     phf4, v4);
                    MMA_F16(oacc[2 * dg],     plf4, v4);
                    MMA_F16(oacc[2 * dg + 1], phf4, v4 + 2);
                    MMA_F16(oacc[2 * dg + 1], plf4, v4 + 2);
                }
            }
        }
        if (++s == 3) s = 0;
    }

    // ---- final row-sum reduce + normalize + write ctx as bf16 hi/lo ----
    ls0 += __shfl_xor_sync(0xffffffffu, ls0, 1);
    ls0 += __shfl_xor_sync(0xffffffffu, ls0, 2);
    ls1 += __shfl_xor_sync(0xffffffffu, ls1, 1);
    ls1 += __shfl_xor_sync(0xffffffffu, ls1, 2);
    const float inv0 = 1.0f / ls0, inv1 = 1.0f / ls1;
    const size_t tr0 = (size_t)(b * Ss + qt * AQT + w * 16 + (lane >> 2));
    const int dcol = h * Hd + (lane & 3) * 2;
#pragma unroll
    for (int nb = 0; nb < 8; nb++) {
        const float o0 = oacc[nb][0] * inv0, o1 = oacc[nb][1] * inv0;
        const float o2 = oacc[nb][2] * inv1, o3 = oacc[nb][3] * inv1;
        const size_t g0 = tr0 * Dd + dcol + nb * 8;
        const size_t g1 = (tr0 + 8) * Dd + dcol + nb * 8;
        uint32_t hh, ll;
        split2(o0, o1, hh, ll);
        *(uint32_t*)(Ch + g0) = hh;
        *(uint32_t*)(Cl + g0) = ll;
        split2(o2, o3, hh, ll);
        *(uint32_t*)(Ch + g1) = hh;
        *(uint32_t*)(Cl + g1) = ll;
    }
}

// ---------------------------------------------------------------------------
extern "C" void kernel_launch(void* const* d_in, const int* in_sizes, int n_in,
                              void* d_out, int out_size)
{
    const float* x  = (const float*)d_in[0];
    const float* Wq = (const float*)d_in[1];
    const float* bq = (const float*)d_in[2];
    const float* Wk = (const float*)d_in[3];
    const float* bk = (const float*)d_in[4];
    const float* Wv = (const float*)d_in[5];
    const float* bv = (const float*)d_in[6];
    const float* Wo = (const float*)d_in[7];
    const float* bo = (const float*)d_in[8];
    float* out = (float*)d_out;

    __nv_bfloat16 *xh, *xl, *qh, *ql, *kh, *vh, *ch, *cl, *wth, *wtl;
    cudaGetSymbolAddress((void**)&xh, g_xh);
    cudaGetSymbolAddress((void**)&xl, g_xl);
    cudaGetSymbolAddress((void**)&qh, g_qh);
    cudaGetSymbolAddress((void**)&ql, g_ql);
    cudaGetSymbolAddress((void**)&kh, g_kh);
    cudaGetSymbolAddress((void**)&vh, g_vh);
    cudaGetSymbolAddress((void**)&ch, g_ch);
    cudaGetSymbolAddress((void**)&cl, g_cl);
    cudaGetSymbolAddress((void**)&wth, g_wth);
    cudaGetSymbolAddress((void**)&wtl, g_wtl);

    const int WSZ = Dd * Dd;

    transpose_split4_bf16<<<dim3(32, 32, 4), dim3(32, 8)>>>(Wq, Wk, Wv, Wo, wth, wtl);

    split_hilo_bf16<<<(MM * Dd) / 1024, 256>>>(x, xh, xl);

    // QKV: Q -> fp16 hi/lo (pre-scaled), K -> single fp16, V -> single fp16
    gemm_bf16x3<<<dim3(24, MM / 128), 256, GSMEM>>>(
        xh, xl, wth, wtl, bq, bk, bv,
        qh, ql, kh, nullptr, vh, nullptr, nullptr);

    attn_f16<<<dim3(Ss / AQT, Bb * Hh), 256, ASMEM>>>(qh, ql, kh, vh, ch, cl);

    gemm_bf16x3<<<dim3(8, MM / 128), 256, GSMEM>>>(
        ch, cl, wth + 3 * (size_t)WSZ, wtl + 3 * (size_t)WSZ, bo, bo, bo,
        nullptr, nullptr, nullptr, nullptr, nullptr, nullptr, out);
}